// round 1
// baseline (speedup 1.0000x reference)
#include <cuda_runtime.h>
#include <cstdint>

// ---------------------------------------------------------------------------
// FlowODEv2: tokens -> embed gather -> z0 = x P^T -> 16 ODE steps
//            -> x_out = x + z Q^T -> RMSNorm -> logits = normed LMH^T
// Shapes: B*T = 4096, D = 2048, R = 256, 4R = 1024, TDIM = 64, V = 32000
// ---------------------------------------------------------------------------

#define MT 4096      // B*T rows
#define DD 2048
#define RR 256
#define HH 1024      // 4R
#define TD 64
#define VV 32000
#define NSTEP 16

// Scratch (device globals: allocation-free)
__device__ float g_x[(size_t)MT * DD];       // x, then x_out, then normed (in-place)
__device__ float g_z[(size_t)MT * RR];
__device__ float g_h[(size_t)MT * HH];
__device__ float g_b1eff[NSTEP * HH];
__device__ float g_temb[NSTEP * TD];
__device__ float g_tau[NSTEP];
__device__ int   g_tok64;

// ---------------------------------------------------------------------------
// Token dtype detector: if input is int64 (little-endian, values < 2^31),
// every odd 32-bit word is zero. Reads only 16KB (safe for both layouts).
// ---------------------------------------------------------------------------
__global__ void detect_tok_kernel(const void* tokens) {
    const int* t = (const int*)tokens;
    __shared__ int any;
    if (threadIdx.x == 0) any = 0;
    __syncthreads();
    int bad = 0;
    for (int i = threadIdx.x; i < MT / 2; i += blockDim.x)
        if (t[2 * i + 1] != 0) bad = 1;
    if (bad) any = 1;
    __syncthreads();
    if (threadIdx.x == 0) g_tok64 = any ? 0 : 1;
}

// ---------------------------------------------------------------------------
// time embeddings + tau
// ---------------------------------------------------------------------------
__global__ void temb_kernel(const float* __restrict__ log_tau) {
    int tid = threadIdx.x;
    const float TWO_PI = 6.2831853071795864769f;
    for (int s = 0; s < NSTEP; s++) {
        float t = (float)s / (float)(NSTEP - 1);
        if (tid < 32) {
            g_temb[s * TD + tid] = sinf(t * (float)tid * TWO_PI);
        } else {
            int j = tid - 32;
            g_temb[s * TD + 32 + j] = cosf(t * (float)j * TWO_PI);
        }
    }
    if (tid < NSTEP) g_tau[tid] = expf(log_tau[tid]);
}

// b1_eff[s][h] = b1[h] + sum_j W1[h][256+j] * temb[s][j]
__global__ void b1eff_kernel(const float* __restrict__ W1, const float* __restrict__ b1) {
    int s = blockIdx.y;
    int h = blockIdx.x * 256 + threadIdx.x;
    float acc = b1[h];
    const float* w = W1 + (size_t)h * (RR + TD) + RR;
    const float* te = g_temb + s * TD;
#pragma unroll
    for (int j = 0; j < TD; j++) acc += w[j] * te[j];
    g_b1eff[s * HH + h] = acc;
}

// ---------------------------------------------------------------------------
// embed gather: g_x[row] = embed_w[tokens[row]]
// ---------------------------------------------------------------------------
__global__ void gather_kernel(const void* __restrict__ tokens,
                              const float* __restrict__ embed_w) {
    int row = blockIdx.x;
    long long tok;
    if (g_tok64) tok = ((const long long*)tokens)[row];
    else         tok = (long long)((const int*)tokens)[row];
    const float4* src = (const float4*)(embed_w + (size_t)tok * DD);
    float4* dst = (float4*)(g_x + (size_t)row * DD);
    for (int i = threadIdx.x; i < DD / 4; i += blockDim.x) dst[i] = src[i];
}

// ---------------------------------------------------------------------------
// Generic tiled SGEMM: C[M,N] = epi(A[M,K] @ B[N,K]^T)
//   MODE 0: C = acc (+bias)
//   MODE 1: C = gelu_exact(acc + bias)
//   MODE 2: C = C + alpha * (acc (+bias))
// Requires M%128==0, N%128==0, K%16==0 (true for all call sites).
// ---------------------------------------------------------------------------
#define BM 128
#define BN 128
#define BK 16

template <int MODE>
__global__ __launch_bounds__(256, 2) void sgemm_kernel(
    const float* __restrict__ A, const float* __restrict__ B,
    const float* __restrict__ bias, float* __restrict__ C,
    int M, int N, int K, int lda, int ldb,
    const float* __restrict__ alpha_ptr, float alpha_c) {
    __shared__ float As[BK][BM + 4];
    __shared__ float Bs[BK][BN + 4];

    const int tid = threadIdx.x;
    const int tx = tid & 15;       // 0..15 (cols)
    const int ty = tid >> 4;       // 0..15 (rows)
    const int bm = blockIdx.y * BM;
    const int bn = blockIdx.x * BN;

    const int lrow = tid >> 2;           // 0..63
    const int lc4 = (tid & 3) << 2;      // 0,4,8,12

    const float* Ag = A + (size_t)bm * lda;
    const float* Bg = B + (size_t)bn * ldb;

    float acc[8][8];
#pragma unroll
    for (int i = 0; i < 8; i++)
#pragma unroll
        for (int j = 0; j < 8; j++) acc[i][j] = 0.f;

    for (int k0 = 0; k0 < K; k0 += BK) {
#pragma unroll
        for (int it = 0; it < 2; it++) {
            int r = lrow + it * 64;
            float4 va = *(const float4*)(Ag + (size_t)r * lda + k0 + lc4);
            As[lc4 + 0][r] = va.x; As[lc4 + 1][r] = va.y;
            As[lc4 + 2][r] = va.z; As[lc4 + 3][r] = va.w;
            float4 vb = *(const float4*)(Bg + (size_t)r * ldb + k0 + lc4);
            Bs[lc4 + 0][r] = vb.x; Bs[lc4 + 1][r] = vb.y;
            Bs[lc4 + 2][r] = vb.z; Bs[lc4 + 3][r] = vb.w;
        }
        __syncthreads();
#pragma unroll
        for (int k = 0; k < BK; k++) {
            float4 a0 = *(const float4*)&As[k][ty * 8];
            float4 a1 = *(const float4*)&As[k][ty * 8 + 4];
            float4 b0 = *(const float4*)&Bs[k][tx * 4];
            float4 b1 = *(const float4*)&Bs[k][64 + tx * 4];
            float av[8] = {a0.x, a0.y, a0.z, a0.w, a1.x, a1.y, a1.z, a1.w};
            float bv[8] = {b0.x, b0.y, b0.z, b0.w, b1.x, b1.y, b1.z, b1.w};
#pragma unroll
            for (int i = 0; i < 8; i++)
#pragma unroll
                for (int j = 0; j < 8; j++) acc[i][j] += av[i] * bv[j];
        }
        __syncthreads();
    }

    float alpha = 1.f;
    if (MODE == 2) alpha = alpha_c * (alpha_ptr ? __ldg(alpha_ptr) : 1.f);

#pragma unroll
    for (int i = 0; i < 8; i++) {
        int row = bm + ty * 8 + i;
        size_t rbase = (size_t)row * N;
#pragma unroll
        for (int h = 0; h < 2; h++) {
            int col = bn + h * 64 + tx * 4;
            float* cp = C + rbase + col;
            float v[4];
#pragma unroll
            for (int j = 0; j < 4; j++) {
                v[j] = acc[i][h * 4 + j];
                if (bias) v[j] += bias[col + j];
            }
            if (MODE == 1) {
#pragma unroll
                for (int j = 0; j < 4; j++)
                    v[j] = 0.5f * v[j] * (1.f + erff(v[j] * 0.70710678118654752f));
            }
            if (MODE == 2) {
                float4 cold = *(const float4*)cp;
                v[0] = cold.x + alpha * v[0];
                v[1] = cold.y + alpha * v[1];
                v[2] = cold.z + alpha * v[2];
                v[3] = cold.w + alpha * v[3];
            }
            float4 vo = make_float4(v[0], v[1], v[2], v[3]);
            *(float4*)cp = vo;
        }
    }
}

// ---------------------------------------------------------------------------
// in-place RMSNorm over g_x rows (D=2048), eps = fp32 finfo eps
// ---------------------------------------------------------------------------
__global__ void rmsnorm_kernel(const float* __restrict__ norm_w) {
    int row = blockIdx.x;
    int tid = threadIdx.x;
    float* x = g_x + (size_t)row * DD;
    float4 a = ((const float4*)x)[tid];
    float4 b = ((const float4*)x)[tid + 256];
    float ss = a.x * a.x + a.y * a.y + a.z * a.z + a.w * a.w +
               b.x * b.x + b.y * b.y + b.z * b.z + b.w * b.w;
#pragma unroll
    for (int o = 16; o > 0; o >>= 1) ss += __shfl_xor_sync(0xffffffffu, ss, o);
    __shared__ float red[8];
    if ((tid & 31) == 0) red[tid >> 5] = ss;
    __syncthreads();
    float tot = red[0] + red[1] + red[2] + red[3] + red[4] + red[5] + red[6] + red[7];
    float rms = rsqrtf(tot * (1.f / (float)DD) + 1.1920928955078125e-07f);
    float4 w0 = ((const float4*)norm_w)[tid];
    float4 w1 = ((const float4*)norm_w)[tid + 256];
    a.x *= rms * w0.x; a.y *= rms * w0.y; a.z *= rms * w0.z; a.w *= rms * w0.w;
    b.x *= rms * w1.x; b.y *= rms * w1.y; b.z *= rms * w1.z; b.w *= rms * w1.w;
    ((float4*)x)[tid] = a;
    ((float4*)x)[tid + 256] = b;
}

// ---------------------------------------------------------------------------
extern "C" void kernel_launch(void* const* d_in, const int* in_sizes, int n_in,
                              void* d_out, int out_size) {
    const void*  tokens  = d_in[0];
    const float* embed_w = (const float*)d_in[1];
    const float* lm_head = (const float*)d_in[2];
    const float* norm_w  = (const float*)d_in[3];
    const float* P       = (const float*)d_in[4];
    const float* Q       = (const float*)d_in[5];
    const float* W1      = (const float*)d_in[6];
    const float* b1      = (const float*)d_in[7];
    const float* W2      = (const float*)d_in[8];
    const float* b2      = (const float*)d_in[9];
    const float* log_tau = (const float*)d_in[10];
    float* out = (float*)d_out;

    float *px, *pz, *ph, *pb1eff, *ptau;
    cudaGetSymbolAddress((void**)&px, g_x);
    cudaGetSymbolAddress((void**)&pz, g_z);
    cudaGetSymbolAddress((void**)&ph, g_h);
    cudaGetSymbolAddress((void**)&pb1eff, g_b1eff);
    cudaGetSymbolAddress((void**)&ptau, g_tau);

    detect_tok_kernel<<<1, 256>>>(tokens);
    temb_kernel<<<1, 64>>>(log_tau);
    b1eff_kernel<<<dim3(HH / 256, NSTEP), 256>>>(W1, b1);
    gather_kernel<<<MT, 256>>>(tokens, embed_w);

    // z0 = x @ P^T : M=4096, N=256, K=2048
    sgemm_kernel<0><<<dim3(RR / BN, MT / BM), 256>>>(
        px, P, nullptr, pz, MT, RR, DD, DD, DD, nullptr, 1.f);

    for (int s = 0; s < NSTEP; s++) {
        // h = gelu(z @ W1[:, :256]^T + b1_eff[s]) : M=4096, N=1024, K=256
        sgemm_kernel<1><<<dim3(HH / BN, MT / BM), 256>>>(
            pz, W1, pb1eff + s * HH, ph, MT, HH, RR, RR, RR + TD, nullptr, 1.f);
        // z += 0.01*tau[s]*(h @ W2^T + b2) : M=4096, N=256, K=1024
        sgemm_kernel<2><<<dim3(RR / BN, MT / BM), 256>>>(
            ph, W2, b2, pz, MT, RR, HH, HH, HH, ptau + s, 0.01f);
    }

    // x_out = x + z @ Q^T : M=4096, N=2048, K=256 (accumulate into g_x)
    sgemm_kernel<2><<<dim3(DD / BN, MT / BM), 256>>>(
        pz, Q, nullptr, px, MT, DD, RR, RR, RR, nullptr, 1.f);

    rmsnorm_kernel<<<MT, 256>>>(norm_w);

    // logits = normed @ lm_head^T : M=4096, N=32000, K=2048
    sgemm_kernel<0><<<dim3(VV / BN, MT / BM), 256>>>(
        px, lm_head, nullptr, out, MT, VV, DD, DD, DD, nullptr, 1.f);

    (void)in_sizes; (void)n_in; (void)out_size;
}

// round 7
// speedup vs baseline: 1.8006x; 1.8006x over previous
#include <cuda_runtime.h>
#include <cuda_bf16.h>
#include <cstdint>

// ---------------------------------------------------------------------------
// FlowODEv2: tokens -> embed gather -> z0 = x P^T -> 16 ODE steps
//            -> x_out = x + z Q^T -> RMSNorm -> logits = normed LMH^T
// Logits GEMM on mma.sync bf16 (3-term hi/lo split, fp32 accum).
// NOTE: harness ptxas targets sm_103 (NOT sm_103a) -> tcgen05 unavailable.
// ---------------------------------------------------------------------------

#define MT 4096
#define DD 2048
#define RR 256
#define HH 1024
#define TD 64
#define VV 32000
#define NSTEP 16

// Scratch (device globals: allocation-free)
__device__ float g_x[(size_t)MT * DD];
__device__ float g_z[(size_t)MT * RR];
__device__ float g_h[(size_t)MT * HH];
__device__ float g_b1eff[NSTEP * HH];
__device__ float g_temb[NSTEP * TD];
__device__ float g_tau[NSTEP];
__device__ int   g_tok64;

// bf16 split buffers for the logits GEMM
__device__ __nv_bfloat16 g_lh_hi[(size_t)VV * DD];
__device__ __nv_bfloat16 g_lh_lo[(size_t)VV * DD];
__device__ __nv_bfloat16 g_x_hi[(size_t)MT * DD];
__device__ __nv_bfloat16 g_x_lo[(size_t)MT * DD];

// ---------------------------------------------------------------------------
// PTX helpers (all sm_80-era: legal on sm_103 target)
// ---------------------------------------------------------------------------
__device__ __forceinline__ uint32_t smem_u32(const void* p) {
    uint32_t a;
    asm("{ .reg .u64 t; cvta.to.shared.u64 t, %1; cvt.u32.u64 %0, t; }"
        : "=r"(a) : "l"(p));
    return a;
}
__device__ __forceinline__ void cp_async16(uint32_t sdst, const void* gsrc) {
    asm volatile("cp.async.cg.shared.global [%0], [%1], 16;"
                 :: "r"(sdst), "l"(gsrc) : "memory");
}
__device__ __forceinline__ void cp_async_commit() {
    asm volatile("cp.async.commit_group;" ::: "memory");
}
__device__ __forceinline__ void ldsm4(uint32_t* r, uint32_t addr) {
    asm volatile("ldmatrix.sync.aligned.m8n8.x4.shared.b16 {%0,%1,%2,%3}, [%4];"
                 : "=r"(r[0]), "=r"(r[1]), "=r"(r[2]), "=r"(r[3]) : "r"(addr));
}
__device__ __forceinline__ void mma_bf16(float* c, const uint32_t* a,
                                         uint32_t b0, uint32_t b1) {
    asm volatile("mma.sync.aligned.m16n8k16.row.col.f32.bf16.bf16.f32 "
                 "{%0,%1,%2,%3}, {%4,%5,%6,%7}, {%8,%9}, {%0,%1,%2,%3};"
                 : "+f"(c[0]), "+f"(c[1]), "+f"(c[2]), "+f"(c[3])
                 : "r"(a[0]), "r"(a[1]), "r"(a[2]), "r"(a[3]), "r"(b0), "r"(b1));
}
__device__ __forceinline__ uint32_t sw128(uint32_t off) {
    return off ^ ((off >> 3) & 0x70);
}

// ---------------------------------------------------------------------------
// logits GEMM: C[4096,32000] = Xsplit @ LHsplit^T (fp32 accum)
// CTA 128x128, K-chunk 64 bf16 (128B rows, SW128), double-buffered cp.async.
// 8 warps (2 M x 4 N), warp tile 64x32, mma.m16n8k16 bf16, 3 split terms.
// ---------------------------------------------------------------------------
#define LBM 128
#define LBN 128
#define LKC 64
#define TILE_B 16384                    // one 128x64 bf16 tile (swizzled)
#define STAGE_B (4 * TILE_B)            // Ah | Al | Bh | Bl = 64KB
#define LOGITS_SMEM (2 * STAGE_B)       // 128KB

__global__ __launch_bounds__(256, 1) void logits_mma_kernel(
    const __nv_bfloat16* __restrict__ Ah, const __nv_bfloat16* __restrict__ Al,
    const __nv_bfloat16* __restrict__ Bh, const __nv_bfloat16* __restrict__ Bl,
    float* __restrict__ C) {
    extern __shared__ char smraw[];
    const uint32_t base = smem_u32(smraw);

    const int tid = threadIdx.x;
    const int wid = tid >> 5;
    const int lane = tid & 31;
    const int wm = wid & 1;        // 0..1  (64-row half)
    const int wn = wid >> 1;       // 0..3  (32-col quarter)
    const int bm = blockIdx.x * LBM;
    const int bn = blockIdx.y * LBN;

    // ---- chunk loader: 64KB = 4096 x 16B, 16 per thread --------------------
    auto load_chunk = [&](int k0, int st) {
        const uint32_t sb = base + st * STAGE_B;
#pragma unroll
        for (int i = 0; i < 16; i++) {
            int c = i * 256 + tid;              // 0..4095
            int t = c >> 10;                    // 0:Ah 1:Al 2:Bh 3:Bl
            int w = c & 1023;
            int row = w >> 3;
            int unit = w & 7;
            const __nv_bfloat16* p = (t < 2) ? (t ? Al : Ah) : ((t == 2) ? Bh : Bl);
            int rowbase = (t < 2) ? bm : bn;
            const void* gp = p + (size_t)(rowbase + row) * DD + k0 + unit * 8;
            uint32_t so = sb + t * TILE_B + sw128(row * 128 + unit * 16);
            cp_async16(so, gp);
        }
        cp_async_commit();
    };

    load_chunk(0, 0);
    load_chunk(LKC, 1);

    float acc[4][4][4];                          // [mi][nj][frag]
#pragma unroll
    for (int i = 0; i < 4; i++)
#pragma unroll
        for (int j = 0; j < 4; j++)
#pragma unroll
            for (int f = 0; f < 4; f++) acc[i][j][f] = 0.f;

    const int NCHUNK = DD / LKC;                 // 32

    for (int k = 0; k < NCHUNK; k++) {
        const int st = k & 1;
        if (k < NCHUNK - 1) asm volatile("cp.async.wait_group 1;" ::: "memory");
        else                asm volatile("cp.async.wait_group 0;" ::: "memory");
        __syncthreads();

        const uint32_t sb = base + st * STAGE_B;
        const uint32_t aH = sb;
        const uint32_t aL = sb + TILE_B;
        const uint32_t bH = sb + 2 * TILE_B;
        const uint32_t bL = sb + 3 * TILE_B;

#pragma unroll
        for (int ks = 0; ks < 4; ks++) {
            const int kbyte = ks * 32 + (lane >> 4) * 16;   // k16 step, lane's k-half
            // A fragments (hi + lo), 4 m16 tiles
            uint32_t ah[4][4], al[4][4];
#pragma unroll
            for (int mi = 0; mi < 4; mi++) {
                int row = wm * 64 + mi * 16 + (lane & 15);
                uint32_t off = sw128((uint32_t)(row * 128 + kbyte));
                ldsm4(ah[mi], aH + off);
                ldsm4(al[mi], aL + off);
            }
            // B fragments (hi + lo), 2 n16 blocks covering 32 cols
            uint32_t bh[2][4], bl[2][4];
#pragma unroll
            for (int ni = 0; ni < 2; ni++) {
                int row = wn * 32 + ni * 16 + (lane & 15);
                uint32_t off = sw128((uint32_t)(row * 128 + kbyte));
                ldsm4(bh[ni], bH + off);
                ldsm4(bl[ni], bL + off);
            }
            // 3-term MMAs: Ah*Bh + Ah*Bl + Al*Bh
#pragma unroll
            for (int mi = 0; mi < 4; mi++) {
#pragma unroll
                for (int nj = 0; nj < 4; nj++) {
                    int ni = nj >> 1, hf = nj & 1;
                    // n8 tile from x4: rows0-7 -> {r0,r2}; rows8-15 -> {r1,r3}
                    mma_bf16(acc[mi][nj], ah[mi], bh[ni][hf], bh[ni][hf + 2]);
                    mma_bf16(acc[mi][nj], ah[mi], bl[ni][hf], bl[ni][hf + 2]);
                    mma_bf16(acc[mi][nj], al[mi], bh[ni][hf], bh[ni][hf + 2]);
                }
            }
        }
        __syncthreads();                         // all warps done with stage st
        if (k + 2 < NCHUNK) load_chunk((k + 2) * LKC, st);
    }

    // ---- epilogue: c frag m16n8: (row=lane>>2, col=(lane&3)*2), +8 rows ----
#pragma unroll
    for (int mi = 0; mi < 4; mi++) {
        int row0 = bm + wm * 64 + mi * 16 + (lane >> 2);
#pragma unroll
        for (int nj = 0; nj < 4; nj++) {
            int col = bn + wn * 32 + nj * 8 + (lane & 3) * 2;
            float2* p0 = (float2*)(C + (size_t)row0 * VV + col);
            float2* p1 = (float2*)(C + (size_t)(row0 + 8) * VV + col);
            *p0 = make_float2(acc[mi][nj][0], acc[mi][nj][1]);
            *p1 = make_float2(acc[mi][nj][2], acc[mi][nj][3]);
        }
    }
}

// ---------------------------------------------------------------------------
// bf16 hi/lo split of lm_head
// ---------------------------------------------------------------------------
__global__ void split_lmh_kernel(const float* __restrict__ W) {
    size_t i = (size_t)blockIdx.x * blockDim.x + threadIdx.x;   // float4 index
    size_t n4 = (size_t)VV * DD / 4;
    if (i >= n4) return;
    float4 v = ((const float4*)W)[i];
    float f[4] = {v.x, v.y, v.z, v.w};
    ushort4 hi, lo;
    unsigned short* hp = &hi.x;
    unsigned short* lp = &lo.x;
#pragma unroll
    for (int j = 0; j < 4; j++) {
        __nv_bfloat16 h = __float2bfloat16(f[j]);
        __nv_bfloat16 l = __float2bfloat16(f[j] - __bfloat162float(h));
        hp[j] = *(unsigned short*)&h;
        lp[j] = *(unsigned short*)&l;
    }
    ((ushort4*)g_lh_hi)[i] = hi;
    ((ushort4*)g_lh_lo)[i] = lo;
}

// ---------------------------------------------------------------------------
// Token dtype detector (int64 vs int32)
// ---------------------------------------------------------------------------
__global__ void detect_tok_kernel(const void* tokens) {
    const int* t = (const int*)tokens;
    __shared__ int any;
    if (threadIdx.x == 0) any = 0;
    __syncthreads();
    int bad = 0;
    for (int i = threadIdx.x; i < MT / 2; i += blockDim.x)
        if (t[2 * i + 1] != 0) bad = 1;
    if (bad) any = 1;
    __syncthreads();
    if (threadIdx.x == 0) g_tok64 = any ? 0 : 1;
}

__global__ void temb_kernel(const float* __restrict__ log_tau) {
    int tid = threadIdx.x;
    const float TWO_PI = 6.2831853071795864769f;
    for (int s = 0; s < NSTEP; s++) {
        float t = (float)s / (float)(NSTEP - 1);
        if (tid < 32) g_temb[s * TD + tid] = sinf(t * (float)tid * TWO_PI);
        else {
            int j = tid - 32;
            g_temb[s * TD + 32 + j] = cosf(t * (float)j * TWO_PI);
        }
    }
    if (tid < NSTEP) g_tau[tid] = expf(log_tau[tid]);
}

__global__ void b1eff_kernel(const float* __restrict__ W1, const float* __restrict__ b1) {
    int s = blockIdx.y;
    int h = blockIdx.x * 256 + threadIdx.x;
    float acc = b1[h];
    const float* w = W1 + (size_t)h * (RR + TD) + RR;
    const float* te = g_temb + s * TD;
#pragma unroll
    for (int j = 0; j < TD; j++) acc += w[j] * te[j];
    g_b1eff[s * HH + h] = acc;
}

__global__ void gather_kernel(const void* __restrict__ tokens,
                              const float* __restrict__ embed_w) {
    int row = blockIdx.x;
    long long tok;
    if (g_tok64) tok = ((const long long*)tokens)[row];
    else         tok = (long long)((const int*)tokens)[row];
    const float4* src = (const float4*)(embed_w + (size_t)tok * DD);
    float4* dst = (float4*)(g_x + (size_t)row * DD);
    for (int i = threadIdx.x; i < DD / 4; i += blockDim.x) dst[i] = src[i];
}

// ---------------------------------------------------------------------------
// fp32 SGEMM for the small/medium GEMMs
// ---------------------------------------------------------------------------
#define BM 128
#define BN 128
#define BK 16

template <int MODE>
__global__ __launch_bounds__(256, 2) void sgemm_kernel(
    const float* __restrict__ A, const float* __restrict__ B,
    const float* __restrict__ bias, float* __restrict__ C,
    int M, int N, int K, int lda, int ldb,
    const float* __restrict__ alpha_ptr, float alpha_c) {
    __shared__ float As[BK][BM + 4];
    __shared__ float Bs[BK][BN + 4];

    const int tid = threadIdx.x;
    const int tx = tid & 15;
    const int ty = tid >> 4;
    const int bm = blockIdx.y * BM;
    const int bn = blockIdx.x * BN;

    const int lrow = tid >> 2;
    const int lc4 = (tid & 3) << 2;

    const float* Ag = A + (size_t)bm * lda;
    const float* Bg = B + (size_t)bn * ldb;

    float acc[8][8];
#pragma unroll
    for (int i = 0; i < 8; i++)
#pragma unroll
        for (int j = 0; j < 8; j++) acc[i][j] = 0.f;

    for (int k0 = 0; k0 < K; k0 += BK) {
#pragma unroll
        for (int it = 0; it < 2; it++) {
            int r = lrow + it * 64;
            float4 va = *(const float4*)(Ag + (size_t)r * lda + k0 + lc4);
            As[lc4 + 0][r] = va.x; As[lc4 + 1][r] = va.y;
            As[lc4 + 2][r] = va.z; As[lc4 + 3][r] = va.w;
            float4 vb = *(const float4*)(Bg + (size_t)r * ldb + k0 + lc4);
            Bs[lc4 + 0][r] = vb.x; Bs[lc4 + 1][r] = vb.y;
            Bs[lc4 + 2][r] = vb.z; Bs[lc4 + 3][r] = vb.w;
        }
        __syncthreads();
#pragma unroll
        for (int k = 0; k < BK; k++) {
            float4 a0 = *(const float4*)&As[k][ty * 8];
            float4 a1 = *(const float4*)&As[k][ty * 8 + 4];
            float4 b0 = *(const float4*)&Bs[k][tx * 4];
            float4 b1 = *(const float4*)&Bs[k][64 + tx * 4];
            float av[8] = {a0.x, a0.y, a0.z, a0.w, a1.x, a1.y, a1.z, a1.w};
            float bv[8] = {b0.x, b0.y, b0.z, b0.w, b1.x, b1.y, b1.z, b1.w};
#pragma unroll
            for (int i = 0; i < 8; i++)
#pragma unroll
                for (int j = 0; j < 8; j++) acc[i][j] += av[i] * bv[j];
        }
        __syncthreads();
    }

    float alpha = 1.f;
    if (MODE == 2) alpha = alpha_c * (alpha_ptr ? __ldg(alpha_ptr) : 1.f);

#pragma unroll
    for (int i = 0; i < 8; i++) {
        int row = bm + ty * 8 + i;
        size_t rbase = (size_t)row * N;
#pragma unroll
        for (int h = 0; h < 2; h++) {
            int col = bn + h * 64 + tx * 4;
            float* cp = C + rbase + col;
            float v[4];
#pragma unroll
            for (int j = 0; j < 4; j++) {
                v[j] = acc[i][h * 4 + j];
                if (bias) v[j] += bias[col + j];
            }
            if (MODE == 1) {
#pragma unroll
                for (int j = 0; j < 4; j++)
                    v[j] = 0.5f * v[j] * (1.f + erff(v[j] * 0.70710678118654752f));
            }
            if (MODE == 2) {
                float4 cold = *(const float4*)cp;
                v[0] = cold.x + alpha * v[0];
                v[1] = cold.y + alpha * v[1];
                v[2] = cold.z + alpha * v[2];
                v[3] = cold.w + alpha * v[3];
            }
            *(float4*)cp = make_float4(v[0], v[1], v[2], v[3]);
        }
    }
}

// ---------------------------------------------------------------------------
// RMSNorm over g_x rows; emits bf16 hi/lo split of normed directly
// ---------------------------------------------------------------------------
__global__ void rmsnorm_split_kernel(const float* __restrict__ norm_w) {
    int row = blockIdx.x;
    int tid = threadIdx.x;
    const float* x = g_x + (size_t)row * DD;
    float4 a = ((const float4*)x)[tid];
    float4 b = ((const float4*)x)[tid + 256];
    float ss = a.x * a.x + a.y * a.y + a.z * a.z + a.w * a.w +
               b.x * b.x + b.y * b.y + b.z * b.z + b.w * b.w;
#pragma unroll
    for (int o = 16; o > 0; o >>= 1) ss += __shfl_xor_sync(0xffffffffu, ss, o);
    __shared__ float red[8];
    if ((tid & 31) == 0) red[tid >> 5] = ss;
    __syncthreads();
    float tot = red[0] + red[1] + red[2] + red[3] + red[4] + red[5] + red[6] + red[7];
    float rms = rsqrtf(tot * (1.f / (float)DD) + 1.1920928955078125e-07f);
    float4 w0 = ((const float4*)norm_w)[tid];
    float4 w1 = ((const float4*)norm_w)[tid + 256];
    float va[8] = {a.x * rms * w0.x, a.y * rms * w0.y, a.z * rms * w0.z, a.w * rms * w0.w,
                   b.x * rms * w1.x, b.y * rms * w1.y, b.z * rms * w1.z, b.w * rms * w1.w};
    ushort4 hi[2], lo[2];
#pragma unroll
    for (int g = 0; g < 2; g++) {
        unsigned short* hp = &hi[g].x;
        unsigned short* lp = &lo[g].x;
#pragma unroll
        for (int j = 0; j < 4; j++) {
            float f = va[g * 4 + j];
            __nv_bfloat16 h = __float2bfloat16(f);
            __nv_bfloat16 l = __float2bfloat16(f - __bfloat162float(h));
            hp[j] = *(unsigned short*)&h;
            lp[j] = *(unsigned short*)&l;
        }
    }
    size_t r4 = (size_t)row * (DD / 4);
    ((ushort4*)g_x_hi)[r4 + tid] = hi[0];
    ((ushort4*)g_x_hi)[r4 + tid + 256] = hi[1];
    ((ushort4*)g_x_lo)[r4 + tid] = lo[0];
    ((ushort4*)g_x_lo)[r4 + tid + 256] = lo[1];
}

// ---------------------------------------------------------------------------
extern "C" void kernel_launch(void* const* d_in, const int* in_sizes, int n_in,
                              void* d_out, int out_size) {
    const void*  tokens  = d_in[0];
    const float* embed_w = (const float*)d_in[1];
    const float* lm_head = (const float*)d_in[2];
    const float* norm_w  = (const float*)d_in[3];
    const float* P       = (const float*)d_in[4];
    const float* Q       = (const float*)d_in[5];
    const float* W1      = (const float*)d_in[6];
    const float* b1      = (const float*)d_in[7];
    const float* W2      = (const float*)d_in[8];
    const float* b2      = (const float*)d_in[9];
    const float* log_tau = (const float*)d_in[10];
    float* out = (float*)d_out;

    float *px, *pz, *ph, *pb1eff, *ptau;
    __nv_bfloat16 *pxh, *pxl, *plh, *pll;
    cudaGetSymbolAddress((void**)&px, g_x);
    cudaGetSymbolAddress((void**)&pz, g_z);
    cudaGetSymbolAddress((void**)&ph, g_h);
    cudaGetSymbolAddress((void**)&pb1eff, g_b1eff);
    cudaGetSymbolAddress((void**)&ptau, g_tau);
    cudaGetSymbolAddress((void**)&pxh, g_x_hi);
    cudaGetSymbolAddress((void**)&pxl, g_x_lo);
    cudaGetSymbolAddress((void**)&plh, g_lh_hi);
    cudaGetSymbolAddress((void**)&pll, g_lh_lo);

    cudaFuncSetAttribute(logits_mma_kernel,
                         cudaFuncAttributeMaxDynamicSharedMemorySize, LOGITS_SMEM);

    detect_tok_kernel<<<1, 256>>>(tokens);
    temb_kernel<<<1, 64>>>(log_tau);
    b1eff_kernel<<<dim3(HH / 256, NSTEP), 256>>>(W1, b1);
    gather_kernel<<<MT, 256>>>(tokens, embed_w);

    // lm_head split (independent of ODE chain)
    {
        size_t n4 = (size_t)VV * DD / 4;
        int grid = (int)((n4 + 255) / 256);
        split_lmh_kernel<<<grid, 256>>>(lm_head);
    }

    // z0 = x @ P^T
    sgemm_kernel<0><<<dim3(RR / BN, MT / BM), 256>>>(
        px, P, nullptr, pz, MT, RR, DD, DD, DD, nullptr, 1.f);

    for (int s = 0; s < NSTEP; s++) {
        sgemm_kernel<1><<<dim3(HH / BN, MT / BM), 256>>>(
            pz, W1, pb1eff + s * HH, ph, MT, HH, RR, RR, RR + TD, nullptr, 1.f);
        sgemm_kernel<2><<<dim3(RR / BN, MT / BM), 256>>>(
            ph, W2, b2, pz, MT, RR, HH, HH, HH, ptau + s, 0.01f);
    }

    // x_out = x + z @ Q^T
    sgemm_kernel<2><<<dim3(DD / BN, MT / BM), 256>>>(
        pz, Q, nullptr, px, MT, DD, RR, RR, RR, nullptr, 1.f);

    rmsnorm_split_kernel<<<MT, 256>>>(norm_w);

    // logits on tensor cores (mma.sync bf16, 3-term split)
    logits_mma_kernel<<<dim3(MT / LBM, VV / LBN), 256, LOGITS_SMEM>>>(
        pxh, pxl, plh, pll, out);

    (void)in_sizes; (void)n_in; (void)out_size;
}

// round 8
// speedup vs baseline: 2.3145x; 1.2854x over previous
#include <cuda_runtime.h>
#include <cuda_bf16.h>
#include <cstdint>

// ---------------------------------------------------------------------------
// FlowODEv2 — ALL GEMMs on mma.sync bf16 (3-term hi/lo split, fp32 accum).
// Harness ptxas targets sm_103 (not sm_103a): tcgen05 unavailable; mma.sync is.
// ---------------------------------------------------------------------------

#define MT 4096
#define DD 2048
#define RR 256
#define HH 1024
#define TD 64
#define VV 32000
#define NSTEP 16

// fp32 masters
__device__ float g_x[(size_t)MT * DD];
__device__ float g_z[(size_t)MT * RR];
__device__ float g_b1eff[NSTEP * HH];
__device__ float g_temb[NSTEP * TD];
__device__ float g_tau[NSTEP];
__device__ int   g_tok64;

// bf16 split buffers
__device__ __nv_bfloat16 g_lh_hi[(size_t)VV * DD];
__device__ __nv_bfloat16 g_lh_lo[(size_t)VV * DD];
__device__ __nv_bfloat16 g_x_hi[(size_t)MT * DD];   // embed-x split, later normed split
__device__ __nv_bfloat16 g_x_lo[(size_t)MT * DD];
__device__ __nv_bfloat16 g_z_hi[(size_t)MT * RR];
__device__ __nv_bfloat16 g_z_lo[(size_t)MT * RR];
__device__ __nv_bfloat16 g_h_hi[(size_t)MT * HH];
__device__ __nv_bfloat16 g_h_lo[(size_t)MT * HH];
__device__ __nv_bfloat16 g_p_hi[(size_t)RR * DD];
__device__ __nv_bfloat16 g_p_lo[(size_t)RR * DD];
__device__ __nv_bfloat16 g_q_hi[(size_t)DD * RR];
__device__ __nv_bfloat16 g_q_lo[(size_t)DD * RR];
__device__ __nv_bfloat16 g_w1_hi[(size_t)HH * RR];  // packed K=256 (src stride 320)
__device__ __nv_bfloat16 g_w1_lo[(size_t)HH * RR];
__device__ __nv_bfloat16 g_w2_hi[(size_t)RR * HH];
__device__ __nv_bfloat16 g_w2_lo[(size_t)RR * HH];

// ---------------------------------------------------------------------------
// PTX helpers (sm_80-era: legal on sm_103 target)
// ---------------------------------------------------------------------------
__device__ __forceinline__ uint32_t smem_u32(const void* p) {
    uint32_t a;
    asm("{ .reg .u64 t; cvta.to.shared.u64 t, %1; cvt.u32.u64 %0, t; }"
        : "=r"(a) : "l"(p));
    return a;
}
__device__ __forceinline__ void cp_async16(uint32_t sdst, const void* gsrc) {
    asm volatile("cp.async.cg.shared.global [%0], [%1], 16;"
                 :: "r"(sdst), "l"(gsrc) : "memory");
}
__device__ __forceinline__ void cp_async_commit() {
    asm volatile("cp.async.commit_group;" ::: "memory");
}
__device__ __forceinline__ void ldsm4(uint32_t* r, uint32_t addr) {
    asm volatile("ldmatrix.sync.aligned.m8n8.x4.shared.b16 {%0,%1,%2,%3}, [%4];"
                 : "=r"(r[0]), "=r"(r[1]), "=r"(r[2]), "=r"(r[3]) : "r"(addr));
}
__device__ __forceinline__ void mma_bf16(float* c, const uint32_t* a,
                                         uint32_t b0, uint32_t b1) {
    asm volatile("mma.sync.aligned.m16n8k16.row.col.f32.bf16.bf16.f32 "
                 "{%0,%1,%2,%3}, {%4,%5,%6,%7}, {%8,%9}, {%0,%1,%2,%3};"
                 : "+f"(c[0]), "+f"(c[1]), "+f"(c[2]), "+f"(c[3])
                 : "r"(a[0]), "r"(a[1]), "r"(a[2]), "r"(a[3]), "r"(b0), "r"(b1));
}
__device__ __forceinline__ uint32_t sw128(uint32_t off) {
    return off ^ ((off >> 3) & 0x70);
}

// ---------------------------------------------------------------------------
// Generalized split-bf16 MMA GEMM: acc = Ah·Bh^T + Ah·Bl^T + Al·Bh^T (fp32)
// CTA 128x128, K-chunk 64, SW128, double-buffered cp.async, 8 warps (2Mx4N).
// Epilogue MODE:
//   0: Cf = acc                       (logits)
//   1: Cf = acc; split->Ch/Cl        (z0)
//   2: split(gelu(acc+bias))->Ch/Cl  (h)            [no Cf]
//   3: Cf += 0.01*tau*(acc+bias); split(Cf)->Ch/Cl (z update)
//   4: Cf += acc                      (x residual)
// ---------------------------------------------------------------------------
#define LBM 128
#define LBN 128
#define LKC 64
#define TILE_B 16384
#define STAGE_B (4 * TILE_B)
#define GEMM_SMEM (2 * STAGE_B)

template <int MODE>
__global__ __launch_bounds__(256, 1) void mma_gemm_kernel(
    const __nv_bfloat16* __restrict__ Ah, const __nv_bfloat16* __restrict__ Al,
    const __nv_bfloat16* __restrict__ Bh, const __nv_bfloat16* __restrict__ Bl,
    int lda, int ldb, int K,
    float* __restrict__ Cf, int ldc,
    __nv_bfloat16* __restrict__ Ch, __nv_bfloat16* __restrict__ Cl,
    const float* __restrict__ bias, const float* __restrict__ alpha_ptr) {
    extern __shared__ char smraw[];
    const uint32_t base = smem_u32(smraw);

    const int tid = threadIdx.x;
    const int wid = tid >> 5;
    const int lane = tid & 31;
    const int wm = wid & 1;
    const int wn = wid >> 1;
    const int bm = blockIdx.x * LBM;
    const int bn = blockIdx.y * LBN;

    auto load_chunk = [&](int k0, int st) {
        const uint32_t sb = base + st * STAGE_B;
#pragma unroll
        for (int i = 0; i < 16; i++) {
            int c = i * 256 + tid;
            int t = c >> 10;                    // 0:Ah 1:Al 2:Bh 3:Bl
            int w = c & 1023;
            int row = w >> 3;
            int unit = w & 7;
            const __nv_bfloat16* p = (t < 2) ? (t ? Al : Ah) : ((t == 2) ? Bh : Bl);
            int rowbase = (t < 2) ? bm : bn;
            int ld = (t < 2) ? lda : ldb;
            const void* gp = p + (size_t)(rowbase + row) * ld + k0 + unit * 8;
            uint32_t so = sb + t * TILE_B + sw128(row * 128 + unit * 16);
            cp_async16(so, gp);
        }
        cp_async_commit();
    };

    load_chunk(0, 0);
    load_chunk(LKC, 1);

    float acc[4][4][4];
#pragma unroll
    for (int i = 0; i < 4; i++)
#pragma unroll
        for (int j = 0; j < 4; j++)
#pragma unroll
            for (int f = 0; f < 4; f++) acc[i][j][f] = 0.f;

    const int NCHUNK = K / LKC;

    for (int k = 0; k < NCHUNK; k++) {
        const int st = k & 1;
        if (k < NCHUNK - 1) asm volatile("cp.async.wait_group 1;" ::: "memory");
        else                asm volatile("cp.async.wait_group 0;" ::: "memory");
        __syncthreads();

        const uint32_t sb = base + st * STAGE_B;
        const uint32_t aH = sb;
        const uint32_t aL = sb + TILE_B;
        const uint32_t bH = sb + 2 * TILE_B;
        const uint32_t bL = sb + 3 * TILE_B;

#pragma unroll
        for (int ks = 0; ks < 4; ks++) {
            const int kbyte = ks * 32 + (lane >> 4) * 16;
            uint32_t ah[4][4], al[4][4];
#pragma unroll
            for (int mi = 0; mi < 4; mi++) {
                int row = wm * 64 + mi * 16 + (lane & 15);
                uint32_t off = sw128((uint32_t)(row * 128 + kbyte));
                ldsm4(ah[mi], aH + off);
                ldsm4(al[mi], aL + off);
            }
            uint32_t bh[2][4], bl[2][4];
#pragma unroll
            for (int ni = 0; ni < 2; ni++) {
                int row = wn * 32 + ni * 16 + (lane & 15);
                uint32_t off = sw128((uint32_t)(row * 128 + kbyte));
                ldsm4(bh[ni], bH + off);
                ldsm4(bl[ni], bL + off);
            }
#pragma unroll
            for (int mi = 0; mi < 4; mi++) {
#pragma unroll
                for (int nj = 0; nj < 4; nj++) {
                    int ni = nj >> 1, hf = nj & 1;
                    mma_bf16(acc[mi][nj], ah[mi], bh[ni][hf], bh[ni][hf + 2]);
                    mma_bf16(acc[mi][nj], ah[mi], bl[ni][hf], bl[ni][hf + 2]);
                    mma_bf16(acc[mi][nj], al[mi], bh[ni][hf], bh[ni][hf + 2]);
                }
            }
        }
        __syncthreads();
        if (k + 2 < NCHUNK) load_chunk((k + 2) * LKC, st);
    }

    // ---- epilogue ----------------------------------------------------------
    float alpha = 0.f;
    if (MODE == 3) alpha = 0.01f * __ldg(alpha_ptr);

#pragma unroll
    for (int mi = 0; mi < 4; mi++) {
        int row0 = bm + wm * 64 + mi * 16 + (lane >> 2);
#pragma unroll
        for (int nj = 0; nj < 4; nj++) {
            int col = bn + wn * 32 + nj * 8 + (lane & 3) * 2;
#pragma unroll
            for (int half = 0; half < 2; half++) {
                int r = row0 + half * 8;
                float x = acc[mi][nj][half * 2 + 0];
                float y = acc[mi][nj][half * 2 + 1];
                size_t off = (size_t)r * ldc + col;
                if (MODE == 2 || MODE == 3) { x += bias[col]; y += bias[col + 1]; }
                if (MODE == 2) {
                    x = 0.5f * x * (1.f + erff(x * 0.70710678118654752f));
                    y = 0.5f * y * (1.f + erff(y * 0.70710678118654752f));
                }
                if (MODE == 3) {
                    x = Cf[off] + alpha * x;
                    y = Cf[off + 1] + alpha * y;
                }
                if (MODE == 4) {
                    x += Cf[off];
                    y += Cf[off + 1];
                }
                if (MODE != 2) *(float2*)(Cf + off) = make_float2(x, y);
                if (MODE == 1 || MODE == 2 || MODE == 3) {
                    __nv_bfloat16 hx = __float2bfloat16(x);
                    __nv_bfloat16 hy = __float2bfloat16(y);
                    __nv_bfloat16 lx = __float2bfloat16(x - __bfloat162float(hx));
                    __nv_bfloat16 ly = __float2bfloat16(y - __bfloat162float(hy));
                    __nv_bfloat162 hv; hv.x = hx; hv.y = hy;
                    __nv_bfloat162 lv; lv.x = lx; lv.y = ly;
                    *(__nv_bfloat162*)(Ch + off) = hv;
                    *(__nv_bfloat162*)(Cl + off) = lv;
                }
            }
        }
    }
}

// ---------------------------------------------------------------------------
// generic fp32 -> bf16 hi/lo split (float4 granular)
// ---------------------------------------------------------------------------
__global__ void split_pair_kernel(const float* __restrict__ src,
                                  __nv_bfloat16* __restrict__ dh,
                                  __nv_bfloat16* __restrict__ dl, size_t n4) {
    size_t i = (size_t)blockIdx.x * blockDim.x + threadIdx.x;
    if (i >= n4) return;
    float4 v = ((const float4*)src)[i];
    float f[4] = {v.x, v.y, v.z, v.w};
    ushort4 hi, lo;
    unsigned short* hp = &hi.x;
    unsigned short* lp = &lo.x;
#pragma unroll
    for (int j = 0; j < 4; j++) {
        __nv_bfloat16 h = __float2bfloat16(f[j]);
        __nv_bfloat16 l = __float2bfloat16(f[j] - __bfloat162float(h));
        hp[j] = *(unsigned short*)&h;
        lp[j] = *(unsigned short*)&l;
    }
    ((ushort4*)dh)[i] = hi;
    ((ushort4*)dl)[i] = lo;
}

// W1 strided split: [HH rows, src stride RR+TD, first RR cols] -> packed [HH,RR]
__global__ void split_w1_kernel(const float* __restrict__ W1) {
    int h = blockIdx.x;
    int t = threadIdx.x;   // 0..63, 4 cols each
    float4 v = *(const float4*)(W1 + (size_t)h * (RR + TD) + t * 4);
    float f[4] = {v.x, v.y, v.z, v.w};
    ushort4 hi, lo;
    unsigned short* hp = &hi.x;
    unsigned short* lp = &lo.x;
#pragma unroll
    for (int j = 0; j < 4; j++) {
        __nv_bfloat16 hb = __float2bfloat16(f[j]);
        __nv_bfloat16 lb = __float2bfloat16(f[j] - __bfloat162float(hb));
        hp[j] = *(unsigned short*)&hb;
        lp[j] = *(unsigned short*)&lb;
    }
    ((ushort4*)g_w1_hi)[h * (RR / 4) + t] = hi;
    ((ushort4*)g_w1_lo)[h * (RR / 4) + t] = lo;
}

// ---------------------------------------------------------------------------
// small kernels
// ---------------------------------------------------------------------------
__global__ void detect_tok_kernel(const void* tokens) {
    const int* t = (const int*)tokens;
    __shared__ int any;
    if (threadIdx.x == 0) any = 0;
    __syncthreads();
    int bad = 0;
    for (int i = threadIdx.x; i < MT / 2; i += blockDim.x)
        if (t[2 * i + 1] != 0) bad = 1;
    if (bad) any = 1;
    __syncthreads();
    if (threadIdx.x == 0) g_tok64 = any ? 0 : 1;
}

__global__ void temb_kernel(const float* __restrict__ log_tau) {
    int tid = threadIdx.x;
    const float TWO_PI = 6.2831853071795864769f;
    for (int s = 0; s < NSTEP; s++) {
        float t = (float)s / (float)(NSTEP - 1);
        if (tid < 32) g_temb[s * TD + tid] = sinf(t * (float)tid * TWO_PI);
        else {
            int j = tid - 32;
            g_temb[s * TD + 32 + j] = cosf(t * (float)j * TWO_PI);
        }
    }
    if (tid < NSTEP) g_tau[tid] = expf(log_tau[tid]);
}

__global__ void b1eff_kernel(const float* __restrict__ W1, const float* __restrict__ b1) {
    int s = blockIdx.y;
    int h = blockIdx.x * 256 + threadIdx.x;
    float acc = b1[h];
    const float* w = W1 + (size_t)h * (RR + TD) + RR;
    const float* te = g_temb + s * TD;
#pragma unroll
    for (int j = 0; j < TD; j++) acc += w[j] * te[j];
    g_b1eff[s * HH + h] = acc;
}

__global__ void gather_kernel(const void* __restrict__ tokens,
                              const float* __restrict__ embed_w) {
    int row = blockIdx.x;
    long long tok;
    if (g_tok64) tok = ((const long long*)tokens)[row];
    else         tok = (long long)((const int*)tokens)[row];
    const float4* src = (const float4*)(embed_w + (size_t)tok * DD);
    float4* dst = (float4*)(g_x + (size_t)row * DD);
    for (int i = threadIdx.x; i < DD / 4; i += blockDim.x) dst[i] = src[i];
}

// RMSNorm over g_x rows; emits bf16 hi/lo split of normed (into g_x_hi/lo)
__global__ void rmsnorm_split_kernel(const float* __restrict__ norm_w) {
    int row = blockIdx.x;
    int tid = threadIdx.x;
    const float* x = g_x + (size_t)row * DD;
    float4 a = ((const float4*)x)[tid];
    float4 b = ((const float4*)x)[tid + 256];
    float ss = a.x * a.x + a.y * a.y + a.z * a.z + a.w * a.w +
               b.x * b.x + b.y * b.y + b.z * b.z + b.w * b.w;
#pragma unroll
    for (int o = 16; o > 0; o >>= 1) ss += __shfl_xor_sync(0xffffffffu, ss, o);
    __shared__ float red[8];
    if ((tid & 31) == 0) red[tid >> 5] = ss;
    __syncthreads();
    float tot = red[0] + red[1] + red[2] + red[3] + red[4] + red[5] + red[6] + red[7];
    float rms = rsqrtf(tot * (1.f / (float)DD) + 1.1920928955078125e-07f);
    float4 w0 = ((const float4*)norm_w)[tid];
    float4 w1 = ((const float4*)norm_w)[tid + 256];
    float va[8] = {a.x * rms * w0.x, a.y * rms * w0.y, a.z * rms * w0.z, a.w * rms * w0.w,
                   b.x * rms * w1.x, b.y * rms * w1.y, b.z * rms * w1.z, b.w * rms * w1.w};
    ushort4 hi[2], lo[2];
#pragma unroll
    for (int g = 0; g < 2; g++) {
        unsigned short* hp = &hi[g].x;
        unsigned short* lp = &lo[g].x;
#pragma unroll
        for (int j = 0; j < 4; j++) {
            float f = va[g * 4 + j];
            __nv_bfloat16 h = __float2bfloat16(f);
            __nv_bfloat16 l = __float2bfloat16(f - __bfloat162float(h));
            hp[j] = *(unsigned short*)&h;
            lp[j] = *(unsigned short*)&l;
        }
    }
    size_t r4 = (size_t)row * (DD / 4);
    ((ushort4*)g_x_hi)[r4 + tid] = hi[0];
    ((ushort4*)g_x_hi)[r4 + tid + 256] = hi[1];
    ((ushort4*)g_x_lo)[r4 + tid] = lo[0];
    ((ushort4*)g_x_lo)[r4 + tid + 256] = lo[1];
}

// ---------------------------------------------------------------------------
extern "C" void kernel_launch(void* const* d_in, const int* in_sizes, int n_in,
                              void* d_out, int out_size) {
    const void*  tokens  = d_in[0];
    const float* embed_w = (const float*)d_in[1];
    const float* lm_head = (const float*)d_in[2];
    const float* norm_w  = (const float*)d_in[3];
    const float* P       = (const float*)d_in[4];
    const float* Q       = (const float*)d_in[5];
    const float* W1      = (const float*)d_in[6];
    const float* b1      = (const float*)d_in[7];
    const float* W2      = (const float*)d_in[8];
    const float* b2      = (const float*)d_in[9];
    const float* log_tau = (const float*)d_in[10];
    float* out = (float*)d_out;

    float *px, *pz, *pb1eff, *ptau;
    cudaGetSymbolAddress((void**)&px, g_x);
    cudaGetSymbolAddress((void**)&pz, g_z);
    cudaGetSymbolAddress((void**)&pb1eff, g_b1eff);
    cudaGetSymbolAddress((void**)&ptau, g_tau);

    __nv_bfloat16 *pxh, *pxl, *plh, *pll, *pzh, *pzl, *phh, *phl;
    __nv_bfloat16 *pph, *ppl, *pqh, *pql, *pw1h, *pw1l, *pw2h, *pw2l;
    cudaGetSymbolAddress((void**)&pxh, g_x_hi);
    cudaGetSymbolAddress((void**)&pxl, g_x_lo);
    cudaGetSymbolAddress((void**)&plh, g_lh_hi);
    cudaGetSymbolAddress((void**)&pll, g_lh_lo);
    cudaGetSymbolAddress((void**)&pzh, g_z_hi);
    cudaGetSymbolAddress((void**)&pzl, g_z_lo);
    cudaGetSymbolAddress((void**)&phh, g_h_hi);
    cudaGetSymbolAddress((void**)&phl, g_h_lo);
    cudaGetSymbolAddress((void**)&pph, g_p_hi);
    cudaGetSymbolAddress((void**)&ppl, g_p_lo);
    cudaGetSymbolAddress((void**)&pqh, g_q_hi);
    cudaGetSymbolAddress((void**)&pql, g_q_lo);
    cudaGetSymbolAddress((void**)&pw1h, g_w1_hi);
    cudaGetSymbolAddress((void**)&pw1l, g_w1_lo);
    cudaGetSymbolAddress((void**)&pw2h, g_w2_hi);
    cudaGetSymbolAddress((void**)&pw2l, g_w2_lo);

    cudaFuncSetAttribute(mma_gemm_kernel<0>, cudaFuncAttributeMaxDynamicSharedMemorySize, GEMM_SMEM);
    cudaFuncSetAttribute(mma_gemm_kernel<1>, cudaFuncAttributeMaxDynamicSharedMemorySize, GEMM_SMEM);
    cudaFuncSetAttribute(mma_gemm_kernel<2>, cudaFuncAttributeMaxDynamicSharedMemorySize, GEMM_SMEM);
    cudaFuncSetAttribute(mma_gemm_kernel<3>, cudaFuncAttributeMaxDynamicSharedMemorySize, GEMM_SMEM);
    cudaFuncSetAttribute(mma_gemm_kernel<4>, cudaFuncAttributeMaxDynamicSharedMemorySize, GEMM_SMEM);

    detect_tok_kernel<<<1, 256>>>(tokens);
    temb_kernel<<<1, 64>>>(log_tau);
    b1eff_kernel<<<dim3(HH / 256, NSTEP), 256>>>(W1, b1);
    gather_kernel<<<MT, 256>>>(tokens, embed_w);

    auto splitn = [](const float* s, __nv_bfloat16* dh, __nv_bfloat16* dl, size_t n) {
        size_t n4 = n / 4;
        split_pair_kernel<<<(unsigned)((n4 + 255) / 256), 256>>>(s, dh, dl, n4);
    };
    splitn(lm_head, plh, pll, (size_t)VV * DD);
    splitn(P, pph, ppl, (size_t)RR * DD);
    splitn(Q, pqh, pql, (size_t)DD * RR);
    splitn(W2, pw2h, pw2l, (size_t)RR * HH);
    split_w1_kernel<<<HH, 64>>>(W1);
    splitn(px, pxh, pxl, (size_t)MT * DD);       // embed-x split

    // z0 = x @ P^T  (MODE 1: fp32 z + split)
    mma_gemm_kernel<1><<<dim3(MT / LBM, RR / LBN), 256, GEMM_SMEM>>>(
        pxh, pxl, pph, ppl, DD, DD, DD, pz, RR, pzh, pzl, nullptr, nullptr);

    for (int s = 0; s < NSTEP; s++) {
        // h = gelu(z @ W1k^T + b1eff[s])  (MODE 2: split h out)
        mma_gemm_kernel<2><<<dim3(MT / LBM, HH / LBN), 256, GEMM_SMEM>>>(
            pzh, pzl, pw1h, pw1l, RR, RR, RR, nullptr, HH, phh, phl,
            pb1eff + s * HH, nullptr);
        // z += 0.01*tau*(h @ W2^T + b2)  (MODE 3)
        mma_gemm_kernel<3><<<dim3(MT / LBM, RR / LBN), 256, GEMM_SMEM>>>(
            phh, phl, pw2h, pw2l, HH, HH, HH, pz, RR, pzh, pzl, b2, ptau + s);
    }

    // x_out = x + z @ Q^T  (MODE 4)
    mma_gemm_kernel<4><<<dim3(MT / LBM, DD / LBN), 256, GEMM_SMEM>>>(
        pzh, pzl, pqh, pql, RR, RR, RR, px, DD, nullptr, nullptr, nullptr, nullptr);

    rmsnorm_split_kernel<<<MT, 256>>>(norm_w);

    // logits = normed @ lm_head^T  (MODE 0)
    mma_gemm_kernel<0><<<dim3(MT / LBM, VV / LBN), 256, GEMM_SMEM>>>(
        pxh, pxl, plh, pll, DD, DD, DD, out, VV, nullptr, nullptr, nullptr, nullptr);

    (void)in_sizes; (void)n_in; (void)out_size;
}